// round 3
// baseline (speedup 1.0000x reference)
#include <cuda_runtime.h>
#include <math.h>

#define SEQ 4096
#define DM  1024
#define NH  16
#define DK  64

// Scratch (allocation-guard-safe device globals): 4 x 16 MB
__device__ float g_Q[SEQ * DM];
__device__ float g_K[SEQ * DM];
__device__ float g_V[SEQ * DM];
__device__ float g_attn[SEQ * DM];

// ---------------------------------------------------------------------------
// GEMM: C[M,N] = A[M,K] @ B[N,K]^T + bias[N]
// Tiles: BM=BN=128, BK=8. Block = 16x16 threads, each computes 8x8.
// M, N divisible by 128; K divisible by 8 (true for all 5 calls here).
// ---------------------------------------------------------------------------
__global__ __launch_bounds__(256) void gemm_abT_kernel(
    const float* __restrict__ A, const float* __restrict__ B,
    const float* __restrict__ bias, float* __restrict__ C,
    int M, int N, int K)
{
    const int BM = 128, BN = 128, BK = 8;
    __shared__ float As[BK][BM];
    __shared__ float Bs[BK][BN];

    int bm0 = blockIdx.y * BM;
    int bn0 = blockIdx.x * BN;
    int tx = threadIdx.x;   // 0..15
    int ty = threadIdx.y;   // 0..15
    int tid = ty * 16 + tx; // 0..255

    // Each thread loads one float4 of A and one float4 of B per k-tile.
    int lrow  = tid >> 1;        // 0..127
    int lcol4 = (tid & 1) * 4;   // 0 or 4

    float acc[8][8];
    #pragma unroll
    for (int i = 0; i < 8; i++)
        #pragma unroll
        for (int j = 0; j < 8; j++)
            acc[i][j] = 0.0f;

    for (int k0 = 0; k0 < K; k0 += BK) {
        float4 av = *(const float4*)&A[(size_t)(bm0 + lrow) * K + k0 + lcol4];
        float4 bv = *(const float4*)&B[(size_t)(bn0 + lrow) * K + k0 + lcol4];
        As[lcol4 + 0][lrow] = av.x;
        As[lcol4 + 1][lrow] = av.y;
        As[lcol4 + 2][lrow] = av.z;
        As[lcol4 + 3][lrow] = av.w;
        Bs[lcol4 + 0][lrow] = bv.x;
        Bs[lcol4 + 1][lrow] = bv.y;
        Bs[lcol4 + 2][lrow] = bv.z;
        Bs[lcol4 + 3][lrow] = bv.w;
        __syncthreads();

        #pragma unroll
        for (int kk = 0; kk < BK; kk++) {
            float a[8], b[8];
            #pragma unroll
            for (int i = 0; i < 8; i++) a[i] = As[kk][ty * 8 + i];
            #pragma unroll
            for (int j = 0; j < 8; j++) b[j] = Bs[kk][tx * 8 + j];
            #pragma unroll
            for (int i = 0; i < 8; i++)
                #pragma unroll
                for (int j = 0; j < 8; j++)
                    acc[i][j] = fmaf(a[i], b[j], acc[i][j]);
        }
        __syncthreads();
    }

    // Vectorized epilogue: two float4 stores per row fragment.
    #pragma unroll
    for (int i = 0; i < 8; i++) {
        int row = bm0 + ty * 8 + i;
        int col = bn0 + tx * 8;
        float4 b0 = *(const float4*)&bias[col];
        float4 b1 = *(const float4*)&bias[col + 4];
        float4 c0 = make_float4(acc[i][0] + b0.x, acc[i][1] + b0.y,
                                acc[i][2] + b0.z, acc[i][3] + b0.w);
        float4 c1 = make_float4(acc[i][4] + b1.x, acc[i][5] + b1.y,
                                acc[i][6] + b1.z, acc[i][7] + b1.w);
        *(float4*)&C[(size_t)row * N + col]     = c0;
        *(float4*)&C[(size_t)row * N + col + 4] = c1;
    }
}

// ---------------------------------------------------------------------------
// Flash-attention-style streaming softmax.
// Block: 128 threads, one query row per thread. grid = (SEQ/128, NH).
// K/V staged in smem in 128-key tiles (64 KB); inner-loop smem reads are
// same-address broadcasts (conflict-free).
// ---------------------------------------------------------------------------
__global__ __launch_bounds__(128) void attn_kernel(
    const float* __restrict__ Q, const float* __restrict__ K,
    const float* __restrict__ V, float* __restrict__ O)
{
    const int TK = 128;  // keys per tile
    __shared__ float Ks[TK][DK];
    __shared__ float Vs[TK][DK];

    int h   = blockIdx.y;
    int row = blockIdx.x * 128 + threadIdx.x;
    int hoff = h * DK;

    const float scale = 0.125f;  // 1/sqrt(64)

    float q[DK];
    #pragma unroll
    for (int d = 0; d < DK; d++)
        q[d] = Q[(size_t)row * DM + hoff + d] * scale;

    float m = -1e30f, l = 0.0f;
    float acc[DK];
    #pragma unroll
    for (int d = 0; d < DK; d++) acc[d] = 0.0f;

    for (int kb = 0; kb < SEQ; kb += TK) {
        // Cooperative tile load: TK rows x 16 float4 per tensor.
        for (int i = threadIdx.x; i < TK * (DK / 4); i += 128) {
            int r  = i >> 4;
            int c4 = (i & 15) * 4;
            *(float4*)&Ks[r][c4] = *(const float4*)&K[(size_t)(kb + r) * DM + hoff + c4];
            *(float4*)&Vs[r][c4] = *(const float4*)&V[(size_t)(kb + r) * DM + hoff + c4];
        }
        __syncthreads();

        #pragma unroll 4
        for (int j = 0; j < TK; j++) {
            float s = 0.0f;
            #pragma unroll
            for (int d = 0; d < DK; d++)
                s = fmaf(q[d], Ks[j][d], s);

            if (s > m) {
                float alpha = __expf(m - s);
                l = l * alpha + 1.0f;
                #pragma unroll
                for (int d = 0; d < DK; d++)
                    acc[d] = fmaf(acc[d], alpha, Vs[j][d]);
                m = s;
            } else {
                float p = __expf(s - m);
                l += p;
                #pragma unroll
                for (int d = 0; d < DK; d++)
                    acc[d] = fmaf(p, Vs[j][d], acc[d]);
            }
        }
        __syncthreads();
    }

    float inv = 1.0f / l;
    #pragma unroll
    for (int d = 0; d < DK; d++)
        O[(size_t)row * DM + hoff + d] = acc[d] * inv;
}

// ---------------------------------------------------------------------------
extern "C" void kernel_launch(void* const* d_in, const int* in_sizes, int n_in,
                              void* d_out, int out_size)
{
    const float* query = (const float*)d_in[0];
    const float* key   = (const float*)d_in[1];
    const float* value = (const float*)d_in[2];
    const float* W_q   = (const float*)d_in[3];
    const float* b_q   = (const float*)d_in[4];
    const float* W_k   = (const float*)d_in[5];
    const float* b_k   = (const float*)d_in[6];
    const float* W_v   = (const float*)d_in[7];
    const float* b_v   = (const float*)d_in[8];
    const float* W_o   = (const float*)d_in[9];
    const float* b_o   = (const float*)d_in[10];
    float* out = (float*)d_out;

    float *Qp, *Kp, *Vp, *Ap;
    cudaGetSymbolAddress((void**)&Qp, g_Q);
    cudaGetSymbolAddress((void**)&Kp, g_K);
    cudaGetSymbolAddress((void**)&Vp, g_V);
    cudaGetSymbolAddress((void**)&Ap, g_attn);

    dim3 gblk(16, 16);
    dim3 ggrd(DM / 128, SEQ / 128);

    // Projections: X @ W^T + b
    gemm_abT_kernel<<<ggrd, gblk>>>(query, W_q, b_q, Qp, SEQ, DM, DM);
    gemm_abT_kernel<<<ggrd, gblk>>>(key,   W_k, b_k, Kp, SEQ, DM, DM);
    gemm_abT_kernel<<<ggrd, gblk>>>(value, W_v, b_v, Vp, SEQ, DM, DM);

    // Attention
    dim3 agrd(SEQ / 128, NH);
    attn_kernel<<<agrd, 128>>>(Qp, Kp, Vp, Ap);

    // Output projection
    gemm_abT_kernel<<<ggrd, gblk>>>(Ap, W_o, b_o, out, SEQ, DM, DM);
}

// round 5
// speedup vs baseline: 3.3033x; 3.3033x over previous
#include <cuda_runtime.h>
#include <cuda_bf16.h>
#include <cuda_fp16.h>
#include <math.h>

#define SEQ 4096
#define DM  1024
#define NH  16
#define DK  64

// Scratch (allocation-guard-safe device globals)
__device__ float g_Q[SEQ * DM];
__device__ float g_K[SEQ * DM];
__device__ float g_V[SEQ * DM];
__device__ float g_attn[SEQ * DM];

// ---------------------------------------------------------------------------
// PTX helpers
// ---------------------------------------------------------------------------
__device__ __forceinline__ unsigned cvt_tf32(float f) {
    unsigned r; asm("cvt.rna.tf32.f32 %0, %1;" : "=r"(r) : "f"(f)); return r;
}
__device__ __forceinline__ void mma_tf32(float* c, const unsigned* a,
                                         unsigned b0, unsigned b1) {
    asm volatile(
        "mma.sync.aligned.m16n8k8.row.col.f32.tf32.tf32.f32 "
        "{%0,%1,%2,%3}, {%4,%5,%6,%7}, {%8,%9}, {%0,%1,%2,%3};"
        : "+f"(c[0]), "+f"(c[1]), "+f"(c[2]), "+f"(c[3])
        : "r"(a[0]), "r"(a[1]), "r"(a[2]), "r"(a[3]), "r"(b0), "r"(b1));
}
__device__ __forceinline__ void mma_bf16(float* c, const unsigned* a,
                                         unsigned b0, unsigned b1) {
    asm volatile(
        "mma.sync.aligned.m16n8k16.row.col.f32.bf16.bf16.f32 "
        "{%0,%1,%2,%3}, {%4,%5,%6,%7}, {%8,%9}, {%0,%1,%2,%3};"
        : "+f"(c[0]), "+f"(c[1]), "+f"(c[2]), "+f"(c[3])
        : "r"(a[0]), "r"(a[1]), "r"(a[2]), "r"(a[3]), "r"(b0), "r"(b1));
}
__device__ __forceinline__ void mma_f16(float* c, const unsigned* a,
                                        unsigned b0, unsigned b1) {
    asm volatile(
        "mma.sync.aligned.m16n8k16.row.col.f32.f16.f16.f32 "
        "{%0,%1,%2,%3}, {%4,%5,%6,%7}, {%8,%9}, {%0,%1,%2,%3};"
        : "+f"(c[0]), "+f"(c[1]), "+f"(c[2]), "+f"(c[3])
        : "r"(a[0]), "r"(a[1]), "r"(a[2]), "r"(a[3]), "r"(b0), "r"(b1));
}
// packed f16x2: low half = lo, high half = hi
__device__ __forceinline__ unsigned pack_f16(float lo, float hi) {
    unsigned r; asm("cvt.rn.f16x2.f32 %0, %1, %2;" : "=r"(r) : "f"(hi), "f"(lo));
    return r;
}
__device__ __forceinline__ float ex2(float x) {
    float r; asm("ex2.approx.ftz.f32 %0, %1;" : "=f"(r) : "f"(x)); return r;
}
// bf16 hi/lo split of a float2 -> packed bf16x2 hi and lo
__device__ __forceinline__ void bsplit(float2 f, unsigned& hi, unsigned& lo) {
    __nv_bfloat162 h = __float22bfloat162_rn(f);
    float2 hf = __bfloat1622float2(h);
    __nv_bfloat162 l = __float22bfloat162_rn(make_float2(f.x - hf.x, f.y - hf.y));
    hi = *(unsigned*)&h;
    lo = *(unsigned*)&l;
}

// ---------------------------------------------------------------------------
// bf16-split tensor-core GEMM: C[M,N] = A[M,K] @ B[N,K]^T + bias[N]
// A,B held fp32 in smem; split to bf16 hi/lo at fragment load.
// 3 MMAs per k16 step: Ah*Bh + Ah*Bl + Al*Bh  (error ~2^-18, near-fp32).
// Block: 256 threads (8 warps, 4x2). Tile 128x128x32, double-buffered.
// ---------------------------------------------------------------------------
#define GP 40          // padded smem row stride (words): 8*r+2p conflict-free
#define GBUF (128 * GP)

__global__ __launch_bounds__(256) void gemm_bf16x3(
    const float* __restrict__ A, const float* __restrict__ B,
    const float* __restrict__ bias, float* __restrict__ C,
    int M, int N, int Kd)
{
    extern __shared__ float smem[];
    float* sA = smem;              // [2][128*GP]
    float* sB = smem + 2 * GBUF;   // [2][128*GP]

    const int tid  = threadIdx.x;
    const int lane = tid & 31;
    const int warp = tid >> 5;
    const int wy = warp & 3;          // m: 4 warps of 32 rows
    const int wx = warp >> 2;         // n: 2 warps of 64 cols
    const int bm0 = blockIdx.y * 128;
    const int bn0 = blockIdx.x * 128;

    const int lr = tid >> 3;          // 0..31
    const int lc = (tid & 7) << 2;    // 0..28

    float acc[2][8][4];
    #pragma unroll
    for (int mf = 0; mf < 2; mf++)
        #pragma unroll
        for (int nf = 0; nf < 8; nf++)
            #pragma unroll
            for (int i = 0; i < 4; i++) acc[mf][nf][i] = 0.0f;

    // prologue: tile 0 -> buffer 0
    #pragma unroll
    for (int p = 0; p < 4; p++) {
        int row = lr + 32 * p;
        *(float4*)&sA[row * GP + lc] = *(const float4*)(A + (size_t)(bm0 + row) * Kd + lc);
        *(float4*)&sB[row * GP + lc] = *(const float4*)(B + (size_t)(bn0 + row) * Kd + lc);
    }
    __syncthreads();

    const int NT = Kd >> 5;
    float4 ra[4], rb[4];
    const int p2 = (lane & 3) << 1;       // pair offset in words
    const int arow = wy * 32 + (lane >> 2);
    const int brow = wx * 64 + (lane >> 2);

    for (int kt = 0; kt < NT; kt++) {
        const int buf = kt & 1;
        if (kt + 1 < NT) {
            #pragma unroll
            for (int p = 0; p < 4; p++) {
                int row = lr + 32 * p;
                ra[p] = *(const float4*)(A + (size_t)(bm0 + row) * Kd + (kt + 1) * 32 + lc);
                rb[p] = *(const float4*)(B + (size_t)(bn0 + row) * Kd + (kt + 1) * 32 + lc);
            }
        }
        const float* cA = sA + buf * GBUF;
        const float* cB = sB + buf * GBUF;

        #pragma unroll
        for (int ks = 0; ks < 2; ks++) {        // two k16 steps per k32 tile
            const int ko = ks * 16;
            unsigned ah[2][4], al[2][4];
            #pragma unroll
            for (int mf = 0; mf < 2; mf++) {
                int r = arow + mf * 16;
                bsplit(*(const float2*)&cA[r * GP + ko + p2],           ah[mf][0], al[mf][0]);
                bsplit(*(const float2*)&cA[(r + 8) * GP + ko + p2],     ah[mf][1], al[mf][1]);
                bsplit(*(const float2*)&cA[r * GP + ko + 8 + p2],       ah[mf][2], al[mf][2]);
                bsplit(*(const float2*)&cA[(r + 8) * GP + ko + 8 + p2], ah[mf][3], al[mf][3]);
            }
            #pragma unroll
            for (int nf = 0; nf < 8; nf++) {
                int r = brow + nf * 8;
                unsigned bh0, bl0, bh1, bl1;
                bsplit(*(const float2*)&cB[r * GP + ko + p2],     bh0, bl0);
                bsplit(*(const float2*)&cB[r * GP + ko + 8 + p2], bh1, bl1);
                #pragma unroll
                for (int mf = 0; mf < 2; mf++) {
                    mma_bf16(acc[mf][nf], ah[mf], bh0, bh1);
                    mma_bf16(acc[mf][nf], al[mf], bh0, bh1);
                    mma_bf16(acc[mf][nf], ah[mf], bl0, bl1);
                }
            }
        }

        if (kt + 1 < NT) {
            float* nA = sA + (1 - buf) * GBUF;
            float* nB = sB + (1 - buf) * GBUF;
            #pragma unroll
            for (int p = 0; p < 4; p++) {
                int row = lr + 32 * p;
                *(float4*)&nA[row * GP + lc] = ra[p];
                *(float4*)&nB[row * GP + lc] = rb[p];
            }
        }
        __syncthreads();
    }

    // epilogue with bias
    #pragma unroll
    for (int mf = 0; mf < 2; mf++) {
        #pragma unroll
        for (int nf = 0; nf < 8; nf++) {
            int r  = bm0 + wy * 32 + mf * 16 + (lane >> 2);
            int cc = bn0 + wx * 64 + nf * 8 + 2 * (lane & 3);
            float bv0 = bias[cc], bv1 = bias[cc + 1];
            float2 v0 = make_float2(acc[mf][nf][0] + bv0, acc[mf][nf][1] + bv1);
            float2 v1 = make_float2(acc[mf][nf][2] + bv0, acc[mf][nf][3] + bv1);
            *(float2*)(C + (size_t)r * N + cc)       = v0;
            *(float2*)(C + (size_t)(r + 8) * N + cc) = v1;
        }
    }
}

// ---------------------------------------------------------------------------
// Tensor-core flash attention.
// QK^T: tf32 mma with Q split hi/lo (2 mmas), K single tf32.
// Softmax: fp32, base-2. P*V: fp16 mma (accum-frag reuse trick).
// Block: 128 threads (4 warps), 64 query rows, 64-key tiles.
// ---------------------------------------------------------------------------
#define KSP 68     // K/Q smem row stride (words)
#define VSP 72     // Vt smem row stride (fp16 elems)

__global__ __launch_bounds__(128) void fattn_kernel(
    const float* __restrict__ Q, const float* __restrict__ K,
    const float* __restrict__ V, float* __restrict__ O)
{
    __shared__ unsigned sK[64 * KSP];     // fp32 (Q stage) then tf32 bits (K)
    __shared__ __half   sVt[DK * VSP];    // V transposed, fp16

    const int tid  = threadIdx.x;
    const int lane = tid & 31;
    const int warp = tid >> 5;
    const int h    = blockIdx.y;
    const int q0   = blockIdx.x * 64;
    const int hoff = h * DK;

    const float SC = 0.125f * 1.4426950408889634f;   // 1/sqrt(64) * log2(e)

    const int srow = tid >> 4;            // 0..7 per pass
    const int sc4  = (tid & 15) << 2;     // 0..60

    // ---- stage scaled Q (raw fp32) in sK, lift to tf32 hi/lo fragments
    #pragma unroll
    for (int p = 0; p < 8; p++) {
        int r = srow + 8 * p;
        float4 v = *(const float4*)(Q + (size_t)(q0 + r) * DM + hoff + sc4);
        float4 sv = make_float4(v.x * SC, v.y * SC, v.z * SC, v.w * SC);
        *(float4*)&sK[r * KSP + sc4] = sv;
    }
    __syncthreads();

    unsigned qfh[8][4], qfl[8][4];
    {
        const int r0 = warp * 16 + (lane >> 2);
        const float* sKf = (const float*)sK;
        #pragma unroll
        for (int kf = 0; kf < 8; kf++) {
            int c = kf * 8 + (lane & 3);
            int idx[4] = { r0 * KSP + c, (r0 + 8) * KSP + c,
                           r0 * KSP + c + 4, (r0 + 8) * KSP + c + 4 };
            #pragma unroll
            for (int i = 0; i < 4; i++) {
                float x = sKf[idx[i]];
                unsigned hb = cvt_tf32(x);
                qfh[kf][i] = hb;
                qfl[kf][i] = cvt_tf32(x - __uint_as_float(hb));
            }
        }
    }
    __syncthreads();

    float o[8][4];
    #pragma unroll
    for (int df = 0; df < 8; df++)
        #pragma unroll
        for (int i = 0; i < 4; i++) o[df][i] = 0.0f;
    float m0 = -1e30f, m1 = -1e30f, l0 = 0.0f, l1 = 0.0f;

    for (int kb = 0; kb < SEQ; kb += 64) {
        // ---- load K (tf32) and V (fp16, transposed) tiles
        #pragma unroll
        for (int p = 0; p < 8; p++) {
            int r = srow + 8 * p;
            float4 kv = *(const float4*)(K + (size_t)(kb + r) * DM + hoff + sc4);
            float4 vv = *(const float4*)(V + (size_t)(kb + r) * DM + hoff + sc4);
            *(uint4*)&sK[r * KSP + sc4] = make_uint4(
                cvt_tf32(kv.x), cvt_tf32(kv.y), cvt_tf32(kv.z), cvt_tf32(kv.w));
            sVt[(sc4 + 0) * VSP + r] = __float2half(vv.x);
            sVt[(sc4 + 1) * VSP + r] = __float2half(vv.y);
            sVt[(sc4 + 2) * VSP + r] = __float2half(vv.z);
            sVt[(sc4 + 3) * VSP + r] = __float2half(vv.w);
        }
        __syncthreads();

        // ---- S = Q * K^T  (Q hi + Q lo passes)
        float s[8][4];
        #pragma unroll
        for (int nf = 0; nf < 8; nf++)
            #pragma unroll
            for (int i = 0; i < 4; i++) s[nf][i] = 0.0f;

        #pragma unroll
        for (int kf = 0; kf < 8; kf++) {
            const int c = kf * 8 + (lane & 3);
            #pragma unroll
            for (int nf = 0; nf < 8; nf++) {
                int r = nf * 8 + (lane >> 2);
                unsigned b0 = sK[r * KSP + c];
                unsigned b1 = sK[r * KSP + c + 4];
                mma_tf32(s[nf], qfh[kf], b0, b1);
                mma_tf32(s[nf], qfl[kf], b0, b1);
            }
        }

        // ---- online softmax (rows: A = lane/4, B = lane/4 + 8)
        float mx0 = -1e30f, mx1 = -1e30f;
        #pragma unroll
        for (int nf = 0; nf < 8; nf++) {
            mx0 = fmaxf(mx0, fmaxf(s[nf][0], s[nf][1]));
            mx1 = fmaxf(mx1, fmaxf(s[nf][2], s[nf][3]));
        }
        mx0 = fmaxf(mx0, __shfl_xor_sync(0xffffffffu, mx0, 1));
        mx0 = fmaxf(mx0, __shfl_xor_sync(0xffffffffu, mx0, 2));
        mx1 = fmaxf(mx1, __shfl_xor_sync(0xffffffffu, mx1, 1));
        mx1 = fmaxf(mx1, __shfl_xor_sync(0xffffffffu, mx1, 2));

        float nm0 = fmaxf(m0, mx0), nm1 = fmaxf(m1, mx1);
        float a0 = ex2(m0 - nm0), a1 = ex2(m1 - nm1);
        m0 = nm0; m1 = nm1;

        unsigned pp[8][2];
        float ps0 = 0.0f, ps1 = 0.0f;
        #pragma unroll
        for (int nf = 0; nf < 8; nf++) {
            float p0 = ex2(s[nf][0] - nm0);
            float p1 = ex2(s[nf][1] - nm0);
            float p2 = ex2(s[nf][2] - nm1);
            float p3 = ex2(s[nf][3] - nm1);
            ps0 += p0 + p1;
            ps1 += p2 + p3;
            pp[nf][0] = pack_f16(p0, p1);
            pp[nf][1] = pack_f16(p2, p3);
        }
        l0 = l0 * a0 + ps0;
        l1 = l1 * a1 + ps1;

        #pragma unroll
        for (int df = 0; df < 8; df++) {
            o[df][0] *= a0; o[df][1] *= a0;
            o[df][2] *= a1; o[df][3] *= a1;
        }

        // ---- O += P * V  (fp16 mma; A-frags are repacked S-accum frags)
        #pragma unroll
        for (int kf2 = 0; kf2 < 4; kf2++) {
            unsigned af[4];
            af[0] = pp[2 * kf2][0];
            af[1] = pp[2 * kf2][1];
            af[2] = pp[2 * kf2 + 1][0];
            af[3] = pp[2 * kf2 + 1][1];
            const int kcol = kf2 * 16 + 2 * (lane & 3);
            #pragma unroll
            for (int df = 0; df < 8; df++) {
                int r = df * 8 + (lane >> 2);
                unsigned b0 = *(const unsigned*)&sVt[r * VSP + kcol];
                unsigned b1 = *(const unsigned*)&sVt[r * VSP + kcol + 8];
                mma_f16(o[df], af, b0, b1);
            }
        }
        __syncthreads();
    }

    // ---- finalize
    l0 += __shfl_xor_sync(0xffffffffu, l0, 1);
    l0 += __shfl_xor_sync(0xffffffffu, l0, 2);
    l1 += __shfl_xor_sync(0xffffffffu, l1, 1);
    l1 += __shfl_xor_sync(0xffffffffu, l1, 2);
    float i0 = 1.0f / l0, i1 = 1.0f / l1;

    const int grow = q0 + warp * 16 + (lane >> 2);
    #pragma unroll
    for (int df = 0; df < 8; df++) {
        int col = hoff + df * 8 + 2 * (lane & 3);
        *(float2*)(O + (size_t)grow * DM + col) =
            make_float2(o[df][0] * i0, o[df][1] * i0);
        *(float2*)(O + (size_t)(grow + 8) * DM + col) =
            make_float2(o[df][2] * i1, o[df][3] * i1);
    }
}

// ---------------------------------------------------------------------------
extern "C" void kernel_launch(void* const* d_in, const int* in_sizes, int n_in,
                              void* d_out, int out_size)
{
    const float* query = (const float*)d_in[0];
    const float* key   = (const float*)d_in[1];
    const float* value = (const float*)d_in[2];
    const float* W_q   = (const float*)d_in[3];
    const float* b_q   = (const float*)d_in[4];
    const float* W_k   = (const float*)d_in[5];
    const float* b_k   = (const float*)d_in[6];
    const float* W_v   = (const float*)d_in[7];
    const float* b_v   = (const float*)d_in[8];
    const float* W_o   = (const float*)d_in[9];
    const float* b_o   = (const float*)d_in[10];
    float* out = (float*)d_out;

    float *Qp, *Kp, *Vp, *Ap;
    cudaGetSymbolAddress((void**)&Qp, g_Q);
    cudaGetSymbolAddress((void**)&Kp, g_K);
    cudaGetSymbolAddress((void**)&Vp, g_V);
    cudaGetSymbolAddress((void**)&Ap, g_attn);

    const int gsmem = 2 * 2 * GBUF * (int)sizeof(float);   // 81920 B
    static int attr_set = 0;
    if (!attr_set) {
        cudaFuncSetAttribute(gemm_bf16x3, cudaFuncAttributeMaxDynamicSharedMemorySize, gsmem);
        attr_set = 1;
    }

    dim3 ggrd(DM / 128, SEQ / 128);
    gemm_bf16x3<<<ggrd, 256, gsmem>>>(query, W_q, b_q, Qp, SEQ, DM, DM);
    gemm_bf16x3<<<ggrd, 256, gsmem>>>(key,   W_k, b_k, Kp, SEQ, DM, DM);
    gemm_bf16x3<<<ggrd, 256, gsmem>>>(value, W_v, b_v, Vp, SEQ, DM, DM);

    dim3 agrd(SEQ / 64, NH);
    fattn_kernel<<<agrd, 128>>>(Qp, Kp, Vp, Ap);

    gemm_bf16x3<<<ggrd, 256, gsmem>>>(Ap, W_o, b_o, out, SEQ, DM, DM);
}

// round 6
// speedup vs baseline: 4.4654x; 1.3518x over previous
#include <cuda_runtime.h>
#include <cuda_bf16.h>
#include <cuda_fp16.h>
#include <math.h>

#define SEQ 4096
#define DM  1024
#define NH  16
#define DK  64

// Scratch (allocation-guard-safe device globals)
__device__ float g_Q[SEQ * DM];
__device__ float g_K[SEQ * DM];
__device__ float g_V[SEQ * DM];
__device__ float g_attn[SEQ * DM];

// ---------------------------------------------------------------------------
// PTX helpers
// ---------------------------------------------------------------------------
__device__ __forceinline__ void mma_bf16(float* c, const unsigned* a,
                                         unsigned b0, unsigned b1) {
    asm volatile(
        "mma.sync.aligned.m16n8k16.row.col.f32.bf16.bf16.f32 "
        "{%0,%1,%2,%3}, {%4,%5,%6,%7}, {%8,%9}, {%0,%1,%2,%3};"
        : "+f"(c[0]), "+f"(c[1]), "+f"(c[2]), "+f"(c[3])
        : "r"(a[0]), "r"(a[1]), "r"(a[2]), "r"(a[3]), "r"(b0), "r"(b1));
}
__device__ __forceinline__ void mma_f16(float* c, const unsigned* a,
                                        unsigned b0, unsigned b1) {
    asm volatile(
        "mma.sync.aligned.m16n8k16.row.col.f32.f16.f16.f32 "
        "{%0,%1,%2,%3}, {%4,%5,%6,%7}, {%8,%9}, {%0,%1,%2,%3};"
        : "+f"(c[0]), "+f"(c[1]), "+f"(c[2]), "+f"(c[3])
        : "r"(a[0]), "r"(a[1]), "r"(a[2]), "r"(a[3]), "r"(b0), "r"(b1));
}
__device__ __forceinline__ void ldsm_x4(unsigned& r0, unsigned& r1,
                                        unsigned& r2, unsigned& r3, unsigned a) {
    asm volatile("ldmatrix.sync.aligned.m8n8.x4.shared.b16 {%0,%1,%2,%3}, [%4];"
                 : "=r"(r0), "=r"(r1), "=r"(r2), "=r"(r3) : "r"(a));
}
__device__ __forceinline__ void ldsm_x4_t(unsigned& r0, unsigned& r1,
                                          unsigned& r2, unsigned& r3, unsigned a) {
    asm volatile("ldmatrix.sync.aligned.m8n8.x4.trans.shared.b16 {%0,%1,%2,%3}, [%4];"
                 : "=r"(r0), "=r"(r1), "=r"(r2), "=r"(r3) : "r"(a));
}
// packed f16x2: low half = lo, high half = hi
__device__ __forceinline__ unsigned pack_f16(float lo, float hi) {
    unsigned r; asm("cvt.rn.f16x2.f32 %0, %1, %2;" : "=r"(r) : "f"(hi), "f"(lo));
    return r;
}
__device__ __forceinline__ float ex2(float x) {
    float r; asm("ex2.approx.ftz.f32 %0, %1;" : "=f"(r) : "f"(x)); return r;
}
// bf16 hi/lo split of a float2 -> packed bf16x2 hi and lo
__device__ __forceinline__ void bsplit(float2 f, unsigned& hi, unsigned& lo) {
    __nv_bfloat162 h = __float22bfloat162_rn(f);
    float2 hf = __bfloat1622float2(h);
    __nv_bfloat162 l = __float22bfloat162_rn(make_float2(f.x - hf.x, f.y - hf.y));
    hi = *(unsigned*)&h;
    lo = *(unsigned*)&l;
}

// ---------------------------------------------------------------------------
// bf16-split tensor-core GEMM: C[M,N] = A[M,K] @ B[N,K]^T + bias[N]
// (unchanged from round 5 — validated)
// ---------------------------------------------------------------------------
#define GP 40
#define GBUF (128 * GP)

__global__ __launch_bounds__(256) void gemm_bf16x3(
    const float* __restrict__ A, const float* __restrict__ B,
    const float* __restrict__ bias, float* __restrict__ C,
    int M, int N, int Kd)
{
    extern __shared__ float smem[];
    float* sA = smem;
    float* sB = smem + 2 * GBUF;

    const int tid  = threadIdx.x;
    const int lane = tid & 31;
    const int warp = tid >> 5;
    const int wy = warp & 3;
    const int wx = warp >> 2;
    const int bm0 = blockIdx.y * 128;
    const int bn0 = blockIdx.x * 128;

    const int lr = tid >> 3;
    const int lc = (tid & 7) << 2;

    float acc[2][8][4];
    #pragma unroll
    for (int mf = 0; mf < 2; mf++)
        #pragma unroll
        for (int nf = 0; nf < 8; nf++)
            #pragma unroll
            for (int i = 0; i < 4; i++) acc[mf][nf][i] = 0.0f;

    #pragma unroll
    for (int p = 0; p < 4; p++) {
        int row = lr + 32 * p;
        *(float4*)&sA[row * GP + lc] = *(const float4*)(A + (size_t)(bm0 + row) * Kd + lc);
        *(float4*)&sB[row * GP + lc] = *(const float4*)(B + (size_t)(bn0 + row) * Kd + lc);
    }
    __syncthreads();

    const int NT = Kd >> 5;
    float4 ra[4], rb[4];
    const int p2 = (lane & 3) << 1;
    const int arow = wy * 32 + (lane >> 2);
    const int brow = wx * 64 + (lane >> 2);

    for (int kt = 0; kt < NT; kt++) {
        const int buf = kt & 1;
        if (kt + 1 < NT) {
            #pragma unroll
            for (int p = 0; p < 4; p++) {
                int row = lr + 32 * p;
                ra[p] = *(const float4*)(A + (size_t)(bm0 + row) * Kd + (kt + 1) * 32 + lc);
                rb[p] = *(const float4*)(B + (size_t)(bn0 + row) * Kd + (kt + 1) * 32 + lc);
            }
        }
        const float* cA = sA + buf * GBUF;
        const float* cB = sB + buf * GBUF;

        #pragma unroll
        for (int ks = 0; ks < 2; ks++) {
            const int ko = ks * 16;
            unsigned ah[2][4], al[2][4];
            #pragma unroll
            for (int mf = 0; mf < 2; mf++) {
                int r = arow + mf * 16;
                bsplit(*(const float2*)&cA[r * GP + ko + p2],           ah[mf][0], al[mf][0]);
                bsplit(*(const float2*)&cA[(r + 8) * GP + ko + p2],     ah[mf][1], al[mf][1]);
                bsplit(*(const float2*)&cA[r * GP + ko + 8 + p2],       ah[mf][2], al[mf][2]);
                bsplit(*(const float2*)&cA[(r + 8) * GP + ko + 8 + p2], ah[mf][3], al[mf][3]);
            }
            #pragma unroll
            for (int nf = 0; nf < 8; nf++) {
                int r = brow + nf * 8;
                unsigned bh0, bl0, bh1, bl1;
                bsplit(*(const float2*)&cB[r * GP + ko + p2],     bh0, bl0);
                bsplit(*(const float2*)&cB[r * GP + ko + 8 + p2], bh1, bl1);
                #pragma unroll
                for (int mf = 0; mf < 2; mf++) {
                    mma_bf16(acc[mf][nf], ah[mf], bh0, bh1);
                    mma_bf16(acc[mf][nf], al[mf], bh0, bh1);
                    mma_bf16(acc[mf][nf], ah[mf], bl0, bl1);
                }
            }
        }

        if (kt + 1 < NT) {
            float* nA = sA + (1 - buf) * GBUF;
            float* nB = sB + (1 - buf) * GBUF;
            #pragma unroll
            for (int p = 0; p < 4; p++) {
                int row = lr + 32 * p;
                *(float4*)&nA[row * GP + lc] = ra[p];
                *(float4*)&nB[row * GP + lc] = rb[p];
            }
        }
        __syncthreads();
    }

    #pragma unroll
    for (int mf = 0; mf < 2; mf++) {
        #pragma unroll
        for (int nf = 0; nf < 8; nf++) {
            int r  = bm0 + wy * 32 + mf * 16 + (lane >> 2);
            int cc = bn0 + wx * 64 + nf * 8 + 2 * (lane & 3);
            float bv0 = bias[cc], bv1 = bias[cc + 1];
            float2 v0 = make_float2(acc[mf][nf][0] + bv0, acc[mf][nf][1] + bv1);
            float2 v1 = make_float2(acc[mf][nf][2] + bv0, acc[mf][nf][3] + bv1);
            *(float2*)(C + (size_t)r * N + cc)       = v0;
            *(float2*)(C + (size_t)(r + 8) * N + cc) = v1;
        }
    }
}

// ---------------------------------------------------------------------------
// Tensor-core flash attention, v2.
// 256 threads (8 warps), 128 queries/block, 64-key tiles, double-buffered.
// QK^T: bf16 3-pass (Qh*Kh + Ql*Kh + Qh*Kl). PV: fp16 mma.
// All B-fragments via ldmatrix.x4 (V via .trans — no transposed stores).
// ---------------------------------------------------------------------------
#define KST 72                       // half stride for Kh/Kl/V rows
#define TILE_B (64 * KST * 2)        // 9216 B per plane
#define STAGE_B (3 * TILE_B)         // Kh + Kl + V = 27648 B
#define QST 68                       // float stride for Q staging

__global__ __launch_bounds__(256, 1) void fattn_kernel(
    const float* __restrict__ Q, const float* __restrict__ K,
    const float* __restrict__ V, float* __restrict__ O)
{
    extern __shared__ char dsm[];    // 2 * STAGE_B = 55296 B (Q overlays stage 0)

    const int tid  = threadIdx.x;
    const int lane = tid & 31;
    const int warp = tid >> 5;
    const int h    = blockIdx.y;
    const int q0   = blockIdx.x * 128;
    const int hoff = h * DK;

    const float SC = 0.125f * 1.4426950408889634f;   // 1/sqrt(64) * log2(e)

    const unsigned smem_base = (unsigned)__cvta_generic_to_shared(dsm);

    // ---- stage scaled Q (fp32) into smem overlay, lift to bf16 hi/lo frags
    {
        float* Qs = (float*)dsm;
        int r  = tid >> 1;                   // 0..127
        int c0 = (tid & 1) * 32;
        const float* gq = Q + (size_t)(q0 + r) * DM + hoff + c0;
        #pragma unroll
        for (int j = 0; j < 8; j++) {
            float4 v = *(const float4*)(gq + 4 * j);
            *(float4*)&Qs[r * QST + c0 + 4 * j] =
                make_float4(v.x * SC, v.y * SC, v.z * SC, v.w * SC);
        }
    }
    __syncthreads();

    unsigned qh[4][4], ql[4][4];
    {
        const float* Qs = (const float*)dsm;
        const int r0 = warp * 16 + (lane >> 2);
        #pragma unroll
        for (int s4 = 0; s4 < 4; s4++) {
            int c = 16 * s4 + 2 * (lane & 3);
            bsplit(*(const float2*)&Qs[r0 * QST + c],           qh[s4][0], ql[s4][0]);
            bsplit(*(const float2*)&Qs[(r0 + 8) * QST + c],     qh[s4][1], ql[s4][1]);
            bsplit(*(const float2*)&Qs[r0 * QST + c + 8],       qh[s4][2], ql[s4][2]);
            bsplit(*(const float2*)&Qs[(r0 + 8) * QST + c + 8], qh[s4][3], ql[s4][3]);
        }
    }
    __syncthreads();

    // ---- tile fill machinery: thread -> (row r, 16-col chunk)
    const int fr = tid >> 2;              // 0..63
    const int fc = (tid & 3) * 16;        // 0, 16, 32, 48
    const float* gK = K + (size_t)fr * DM + hoff + fc;
    const float* gV = V + (size_t)fr * DM + hoff + fc;

    float4 rk[4], rv[4];
    #pragma unroll
    for (int j = 0; j < 4; j++) {         // prologue: tile 0
        rk[j] = *(const float4*)(gK + 4 * j);
        rv[j] = *(const float4*)(gV + 4 * j);
    }

    // store current regs into stage buf
    auto store_tile = [&](int buf) {
        __half* kh = (__half*)(dsm + buf * STAGE_B);
        __half* kl = (__half*)(dsm + buf * STAGE_B + TILE_B);
        __half* vv = (__half*)(dsm + buf * STAGE_B + 2 * TILE_B);
        #pragma unroll
        for (int j = 0; j < 4; j++) {
            int c = fc + 4 * j;
            unsigned h0, l0, h1, l1;
            bsplit(make_float2(rk[j].x, rk[j].y), h0, l0);
            bsplit(make_float2(rk[j].z, rk[j].w), h1, l1);
            *(uint2*)&kh[fr * KST + c] = make_uint2(h0, h1);
            *(uint2*)&kl[fr * KST + c] = make_uint2(l0, l1);
            unsigned v0 = pack_f16(rv[j].x, rv[j].y);
            unsigned v1 = pack_f16(rv[j].z, rv[j].w);
            *(uint2*)&vv[fr * KST + c] = make_uint2(v0, v1);
        }
    };
    store_tile(0);
    __syncthreads();

    // per-warp ldmatrix lane offsets (byte offsets within a plane)
    const unsigned k_off = ((8 * ((lane >> 4) & 1) + (lane & 7)) * KST
                            + 8 * ((lane >> 3) & 1)) * 2;
    const unsigned v_off = ((8 * ((lane >> 3) & 1) + (lane & 7)) * KST
                            + 8 * (lane >> 4)) * 2;

    float o[8][4];
    #pragma unroll
    for (int df = 0; df < 8; df++)
        #pragma unroll
        for (int i = 0; i < 4; i++) o[df][i] = 0.0f;
    float m0 = -1e30f, m1 = -1e30f, l0s = 0.0f, l1s = 0.0f;

    const int NTILE = SEQ / 64;
    for (int t = 0; t < NTILE; t++) {
        const int buf = t & 1;
        const unsigned stage = smem_base + buf * STAGE_B;

        // prefetch next tile's globals (latency hidden under MMA phase)
        if (t + 1 < NTILE) {
            const float* nK = gK + (size_t)(t + 1) * 64 * DM;
            const float* nV = gV + (size_t)(t + 1) * 64 * DM;
            #pragma unroll
            for (int j = 0; j < 4; j++) {
                rk[j] = *(const float4*)(nK + 4 * j);
                rv[j] = *(const float4*)(nV + 4 * j);
            }
        }

        // ---- S = Q*K^T (bf16 3-pass)
        float s[8][4];
        #pragma unroll
        for (int nf = 0; nf < 8; nf++)
            #pragma unroll
            for (int i = 0; i < 4; i++) s[nf][i] = 0.0f;

        #pragma unroll
        for (int s4 = 0; s4 < 4; s4++) {
            const int d0 = 16 * s4;
            #pragma unroll
            for (int nfp = 0; nfp < 4; nfp++) {
                const unsigned lo_off = (unsigned)((16 * nfp) * KST + d0) * 2 + k_off;
                unsigned h0, h1, h2, h3, l0, l1, l2, l3;
                ldsm_x4(h0, h1, h2, h3, stage + lo_off);
                ldsm_x4(l0, l1, l2, l3, stage + TILE_B + lo_off);
                mma_bf16(s[2 * nfp],     qh[s4], h0, h1);
                mma_bf16(s[2 * nfp],     ql[s4], h0, h1);
                mma_bf16(s[2 * nfp],     qh[s4], l0, l1);
                mma_bf16(s[2 * nfp + 1], qh[s4], h2, h3);
                mma_bf16(s[2 * nfp + 1], ql[s4], h2, h3);
                mma_bf16(s[2 * nfp + 1], qh[s4], l2, l3);
            }
        }

        // ---- online softmax (rows: A = lane/4, B = lane/4 + 8)
        float mx0 = -1e30f, mx1 = -1e30f;
        #pragma unroll
        for (int nf = 0; nf < 8; nf++) {
            mx0 = fmaxf(mx0, fmaxf(s[nf][0], s[nf][1]));
            mx1 = fmaxf(mx1, fmaxf(s[nf][2], s[nf][3]));
        }
        mx0 = fmaxf(mx0, __shfl_xor_sync(0xffffffffu, mx0, 1));
        mx0 = fmaxf(mx0, __shfl_xor_sync(0xffffffffu, mx0, 2));
        mx1 = fmaxf(mx1, __shfl_xor_sync(0xffffffffu, mx1, 1));
        mx1 = fmaxf(mx1, __shfl_xor_sync(0xffffffffu, mx1, 2));

        float nm0 = fmaxf(m0, mx0), nm1 = fmaxf(m1, mx1);
        float a0 = ex2(m0 - nm0), a1 = ex2(m1 - nm1);
        m0 = nm0; m1 = nm1;

        unsigned pp[8][2];
        float ps0 = 0.0f, ps1 = 0.0f;
        #pragma unroll
        for (int nf = 0; nf < 8; nf++) {
            float p0 = ex2(s[nf][0] - nm0);
            float p1 = ex2(s[nf][1] - nm0);
            float p2 = ex2(s[nf][2] - nm1);
            float p3 = ex2(s[nf][3] - nm1);
            ps0 += p0 + p1;
            ps1 += p2 + p3;
            pp[nf][0] = pack_f16(p0, p1);
            pp[nf][1] = pack_f16(p2, p3);
        }
        l0s = l0s * a0 + ps0;
        l1s = l1s * a1 + ps1;

        #pragma unroll
        for (int df = 0; df < 8; df++) {
            o[df][0] *= a0; o[df][1] *= a0;
            o[df][2] *= a1; o[df][3] *= a1;
        }

        // ---- O += P*V (fp16 mma; V B-frags via ldmatrix.trans)
        #pragma unroll
        for (int kf2 = 0; kf2 < 4; kf2++) {
            unsigned af[4];
            af[0] = pp[2 * kf2][0];
            af[1] = pp[2 * kf2][1];
            af[2] = pp[2 * kf2 + 1][0];
            af[3] = pp[2 * kf2 + 1][1];
            #pragma unroll
            for (int dfp = 0; dfp < 4; dfp++) {
                const unsigned off = (unsigned)((16 * kf2) * KST + 16 * dfp) * 2 + v_off;
                unsigned b0, b1, b2, b3;
                ldsm_x4_t(b0, b1, b2, b3, stage + 2 * TILE_B + off);
                mma_f16(o[2 * dfp],     af, b0, b1);
                mma_f16(o[2 * dfp + 1], af, b2, b3);
            }
        }

        // store prefetched tile into the other buffer
        if (t + 1 < NTILE) store_tile(1 - buf);
        __syncthreads();
    }

    // ---- finalize
    l0s += __shfl_xor_sync(0xffffffffu, l0s, 1);
    l0s += __shfl_xor_sync(0xffffffffu, l0s, 2);
    l1s += __shfl_xor_sync(0xffffffffu, l1s, 1);
    l1s += __shfl_xor_sync(0xffffffffu, l1s, 2);
    float i0 = 1.0f / l0s, i1 = 1.0f / l1s;

    const int grow = q0 + warp * 16 + (lane >> 2);
    #pragma unroll
    for (int df = 0; df < 8; df++) {
        int col = hoff + df * 8 + 2 * (lane & 3);
        *(float2*)(O + (size_t)grow * DM + col) =
            make_float2(o[df][0] * i0, o[df][1] * i0);
        *(float2*)(O + (size_t)(grow + 8) * DM + col) =
            make_float2(o[df][2] * i1, o[df][3] * i1);
    }
}

// ---------------------------------------------------------------------------
extern "C" void kernel_launch(void* const* d_in, const int* in_sizes, int n_in,
                              void* d_out, int out_size)
{
    const float* query = (const float*)d_in[0];
    const float* key   = (const float*)d_in[1];
    const float* value = (const float*)d_in[2];
    const float* W_q   = (const float*)d_in[3];
    const float* b_q   = (const float*)d_in[4];
    const float* W_k   = (const float*)d_in[5];
    const float* b_k   = (const float*)d_in[6];
    const float* W_v   = (const float*)d_in[7];
    const float* b_v   = (const float*)d_in[8];
    const float* W_o   = (const float*)d_in[9];
    const float* b_o   = (const float*)d_in[10];
    float* out = (float*)d_out;

    float *Qp, *Kp, *Vp, *Ap;
    cudaGetSymbolAddress((void**)&Qp, g_Q);
    cudaGetSymbolAddress((void**)&Kp, g_K);
    cudaGetSymbolAddress((void**)&Vp, g_V);
    cudaGetSymbolAddress((void**)&Ap, g_attn);

    const int gsmem = 2 * 2 * GBUF * (int)sizeof(float);   // 81920 B
    const int fsmem = 2 * STAGE_B;                          // 55296 B
    static int attr_set = 0;
    if (!attr_set) {
        cudaFuncSetAttribute(gemm_bf16x3, cudaFuncAttributeMaxDynamicSharedMemorySize, gsmem);
        cudaFuncSetAttribute(fattn_kernel, cudaFuncAttributeMaxDynamicSharedMemorySize, fsmem);
        attr_set = 1;
    }

    dim3 ggrd(DM / 128, SEQ / 128);
    gemm_bf16x3<<<ggrd, 256, gsmem>>>(query, W_q, b_q, Qp, SEQ, DM, DM);
    gemm_bf16x3<<<ggrd, 256, gsmem>>>(key,   W_k, b_k, Kp, SEQ, DM, DM);
    gemm_bf16x3<<<ggrd, 256, gsmem>>>(value, W_v, b_v, Vp, SEQ, DM, DM);

    dim3 agrd(SEQ / 128, NH);
    fattn_kernel<<<agrd, 256, fsmem>>>(Qp, Kp, Vp, Ap);

    gemm_bf16x3<<<ggrd, 256, gsmem>>>(Ap, W_o, b_o, out, SEQ, DM, DM);
}

// round 7
// speedup vs baseline: 4.6462x; 1.0405x over previous
#include <cuda_runtime.h>
#include <cuda_bf16.h>
#include <cuda_fp16.h>
#include <math.h>

#define SEQ 4096
#define DM  1024
#define NH  16
#define DK  64

// Scratch (allocation-guard-safe device globals)
__device__ float         g_Q[SEQ * DM];      // fp32 Q
__device__ __nv_bfloat16 g_Kh[SEQ * DM];     // K bf16 hi plane
__device__ __nv_bfloat16 g_Kl[SEQ * DM];     // K bf16 lo plane
__device__ __half        g_V[SEQ * DM];      // V fp16
__device__ float         g_attn[SEQ * DM];

// ---------------------------------------------------------------------------
// PTX helpers
// ---------------------------------------------------------------------------
__device__ __forceinline__ void mma_bf16(float* c, const unsigned* a,
                                         unsigned b0, unsigned b1) {
    asm volatile(
        "mma.sync.aligned.m16n8k16.row.col.f32.bf16.bf16.f32 "
        "{%0,%1,%2,%3}, {%4,%5,%6,%7}, {%8,%9}, {%0,%1,%2,%3};"
        : "+f"(c[0]), "+f"(c[1]), "+f"(c[2]), "+f"(c[3])
        : "r"(a[0]), "r"(a[1]), "r"(a[2]), "r"(a[3]), "r"(b0), "r"(b1));
}
__device__ __forceinline__ void mma_f16(float* c, const unsigned* a,
                                        unsigned b0, unsigned b1) {
    asm volatile(
        "mma.sync.aligned.m16n8k16.row.col.f32.f16.f16.f32 "
        "{%0,%1,%2,%3}, {%4,%5,%6,%7}, {%8,%9}, {%0,%1,%2,%3};"
        : "+f"(c[0]), "+f"(c[1]), "+f"(c[2]), "+f"(c[3])
        : "r"(a[0]), "r"(a[1]), "r"(a[2]), "r"(a[3]), "r"(b0), "r"(b1));
}
__device__ __forceinline__ void ldsm_x4(unsigned& r0, unsigned& r1,
                                        unsigned& r2, unsigned& r3, unsigned a) {
    asm volatile("ldmatrix.sync.aligned.m8n8.x4.shared.b16 {%0,%1,%2,%3}, [%4];"
                 : "=r"(r0), "=r"(r1), "=r"(r2), "=r"(r3) : "r"(a));
}
__device__ __forceinline__ void ldsm_x4_t(unsigned& r0, unsigned& r1,
                                          unsigned& r2, unsigned& r3, unsigned a) {
    asm volatile("ldmatrix.sync.aligned.m8n8.x4.trans.shared.b16 {%0,%1,%2,%3}, [%4];"
                 : "=r"(r0), "=r"(r1), "=r"(r2), "=r"(r3) : "r"(a));
}
__device__ __forceinline__ unsigned pack_f16(float lo, float hi) {
    unsigned r; asm("cvt.rn.f16x2.f32 %0, %1, %2;" : "=r"(r) : "f"(hi), "f"(lo));
    return r;
}
__device__ __forceinline__ float ex2(float x) {
    float r; asm("ex2.approx.ftz.f32 %0, %1;" : "=f"(r) : "f"(x)); return r;
}
__device__ __forceinline__ void bsplit(float2 f, unsigned& hi, unsigned& lo) {
    __nv_bfloat162 h = __float22bfloat162_rn(f);
    float2 hf = __bfloat1622float2(h);
    __nv_bfloat162 l = __float22bfloat162_rn(make_float2(f.x - hf.x, f.y - hf.y));
    hi = *(unsigned*)&h;
    lo = *(unsigned*)&l;
}
__device__ __forceinline__ void cp16(unsigned dst, const void* src) {
    asm volatile("cp.async.cg.shared.global [%0], [%1], 16;"
                 :: "r"(dst), "l"(src));
}

// ---------------------------------------------------------------------------
// bf16-split tensor-core GEMM: C = A @ B^T + bias.
// OMODE 0: fp32 C.  OMODE 1: bf16 hi/lo planes (C0=hi, C1=lo).  OMODE 2: fp16.
// ---------------------------------------------------------------------------
#define GP 40
#define GBUF (128 * GP)

template <int OMODE>
__global__ __launch_bounds__(256) void gemm_bf16x3(
    const float* __restrict__ A, const float* __restrict__ B,
    const float* __restrict__ bias, void* __restrict__ C0,
    void* __restrict__ C1, int M, int N, int Kd)
{
    extern __shared__ float smem[];
    float* sA = smem;
    float* sB = smem + 2 * GBUF;

    const int tid  = threadIdx.x;
    const int lane = tid & 31;
    const int warp = tid >> 5;
    const int wy = warp & 3;
    const int wx = warp >> 2;
    const int bm0 = blockIdx.y * 128;
    const int bn0 = blockIdx.x * 128;

    const int lr = tid >> 3;
    const int lc = (tid & 7) << 2;

    float acc[2][8][4];
    #pragma unroll
    for (int mf = 0; mf < 2; mf++)
        #pragma unroll
        for (int nf = 0; nf < 8; nf++)
            #pragma unroll
            for (int i = 0; i < 4; i++) acc[mf][nf][i] = 0.0f;

    #pragma unroll
    for (int p = 0; p < 4; p++) {
        int row = lr + 32 * p;
        *(float4*)&sA[row * GP + lc] = *(const float4*)(A + (size_t)(bm0 + row) * Kd + lc);
        *(float4*)&sB[row * GP + lc] = *(const float4*)(B + (size_t)(bn0 + row) * Kd + lc);
    }
    __syncthreads();

    const int NT = Kd >> 5;
    float4 ra[4], rb[4];
    const int p2 = (lane & 3) << 1;
    const int arow = wy * 32 + (lane >> 2);
    const int brow = wx * 64 + (lane >> 2);

    for (int kt = 0; kt < NT; kt++) {
        const int buf = kt & 1;
        if (kt + 1 < NT) {
            #pragma unroll
            for (int p = 0; p < 4; p++) {
                int row = lr + 32 * p;
                ra[p] = *(const float4*)(A + (size_t)(bm0 + row) * Kd + (kt + 1) * 32 + lc);
                rb[p] = *(const float4*)(B + (size_t)(bn0 + row) * Kd + (kt + 1) * 32 + lc);
            }
        }
        const float* cA = sA + buf * GBUF;
        const float* cB = sB + buf * GBUF;

        #pragma unroll
        for (int ks = 0; ks < 2; ks++) {
            const int ko = ks * 16;
            unsigned ah[2][4], al[2][4];
            #pragma unroll
            for (int mf = 0; mf < 2; mf++) {
                int r = arow + mf * 16;
                bsplit(*(const float2*)&cA[r * GP + ko + p2],           ah[mf][0], al[mf][0]);
                bsplit(*(const float2*)&cA[(r + 8) * GP + ko + p2],     ah[mf][1], al[mf][1]);
                bsplit(*(const float2*)&cA[r * GP + ko + 8 + p2],       ah[mf][2], al[mf][2]);
                bsplit(*(const float2*)&cA[(r + 8) * GP + ko + 8 + p2], ah[mf][3], al[mf][3]);
            }
            #pragma unroll
            for (int nf = 0; nf < 8; nf++) {
                int r = brow + nf * 8;
                unsigned bh0, bl0, bh1, bl1;
                bsplit(*(const float2*)&cB[r * GP + ko + p2],     bh0, bl0);
                bsplit(*(const float2*)&cB[r * GP + ko + 8 + p2], bh1, bl1);
                #pragma unroll
                for (int mf = 0; mf < 2; mf++) {
                    mma_bf16(acc[mf][nf], ah[mf], bh0, bh1);
                    mma_bf16(acc[mf][nf], al[mf], bh0, bh1);
                    mma_bf16(acc[mf][nf], ah[mf], bl0, bl1);
                }
            }
        }

        if (kt + 1 < NT) {
            float* nA = sA + (1 - buf) * GBUF;
            float* nB = sB + (1 - buf) * GBUF;
            #pragma unroll
            for (int p = 0; p < 4; p++) {
                int row = lr + 32 * p;
                *(float4*)&nA[row * GP + lc] = ra[p];
                *(float4*)&nB[row * GP + lc] = rb[p];
            }
        }
        __syncthreads();
    }

    #pragma unroll
    for (int mf = 0; mf < 2; mf++) {
        #pragma unroll
        for (int nf = 0; nf < 8; nf++) {
            int r  = bm0 + wy * 32 + mf * 16 + (lane >> 2);
            int cc = bn0 + wx * 64 + nf * 8 + 2 * (lane & 3);
            float bv0 = bias[cc], bv1 = bias[cc + 1];
            float2 v0 = make_float2(acc[mf][nf][0] + bv0, acc[mf][nf][1] + bv1);
            float2 v1 = make_float2(acc[mf][nf][2] + bv0, acc[mf][nf][3] + bv1);
            if (OMODE == 0) {
                float* C = (float*)C0;
                *(float2*)(C + (size_t)r * N + cc)       = v0;
                *(float2*)(C + (size_t)(r + 8) * N + cc) = v1;
            } else if (OMODE == 1) {
                __nv_bfloat16* Ch = (__nv_bfloat16*)C0;
                __nv_bfloat16* Cl = (__nv_bfloat16*)C1;
                unsigned h0, l0, h1, l1;
                bsplit(v0, h0, l0);
                bsplit(v1, h1, l1);
                *(unsigned*)(Ch + (size_t)r * N + cc)       = h0;
                *(unsigned*)(Cl + (size_t)r * N + cc)       = l0;
                *(unsigned*)(Ch + (size_t)(r + 8) * N + cc) = h1;
                *(unsigned*)(Cl + (size_t)(r + 8) * N + cc) = l1;
            } else {
                __half* C = (__half*)C0;
                *(unsigned*)(C + (size_t)r * N + cc)       = pack_f16(v0.x, v0.y);
                *(unsigned*)(C + (size_t)(r + 8) * N + cc) = pack_f16(v1.x, v1.y);
            }
        }
    }
}

// ---------------------------------------------------------------------------
// Tensor-core flash attention, v3: cp.async 3-stage pipeline.
// 256 threads (8 warps), 128 queries/block, 64-key tiles.
// K arrives as precomputed bf16 hi/lo planes, V as fp16 (no in-kernel cvt).
// QK^T: bf16 3-pass. PV: fp16 mma. B-frags via ldmatrix.x4.
// ---------------------------------------------------------------------------
#define KST 72                       // half-element stride (144 B rows)
#define TILE_B (64 * KST * 2)        // 9216 B per plane
#define STAGE_B (3 * TILE_B)         // Kh + Kl + V = 27648 B
#define NSTAGE 3
#define QST 68                       // float stride for Q staging

__global__ __launch_bounds__(256, 1) void fattn_kernel(
    const float* __restrict__ Q, const __nv_bfloat16* __restrict__ Kh,
    const __nv_bfloat16* __restrict__ Kl, const __half* __restrict__ V,
    float* __restrict__ O)
{
    extern __shared__ char dsm[];    // NSTAGE * STAGE_B (Q staging overlays)

    const int tid  = threadIdx.x;
    const int lane = tid & 31;
    const int warp = tid >> 5;
    const int h    = blockIdx.y;
    const int q0   = blockIdx.x * 128;
    const int hoff = h * DK;

    const float SC = 0.125f * 1.4426950408889634f;   // 1/sqrt(64) * log2(e)
    const unsigned smem_base = (unsigned)__cvta_generic_to_shared(dsm);

    // ---- stage scaled Q (fp32) into smem overlay, lift to bf16 hi/lo frags
    {
        float* Qs = (float*)dsm;
        int r  = tid >> 1;
        int c0 = (tid & 1) * 32;
        const float* gq = Q + (size_t)(q0 + r) * DM + hoff + c0;
        #pragma unroll
        for (int j = 0; j < 8; j++) {
            float4 v = *(const float4*)(gq + 4 * j);
            *(float4*)&Qs[r * QST + c0 + 4 * j] =
                make_float4(v.x * SC, v.y * SC, v.z * SC, v.w * SC);
        }
    }
    __syncthreads();

    unsigned qh[4][4], ql[4][4];
    {
        const float* Qs = (const float*)dsm;
        const int r0 = warp * 16 + (lane >> 2);
        #pragma unroll
        for (int s4 = 0; s4 < 4; s4++) {
            int c = 16 * s4 + 2 * (lane & 3);
            bsplit(*(const float2*)&Qs[r0 * QST + c],           qh[s4][0], ql[s4][0]);
            bsplit(*(const float2*)&Qs[(r0 + 8) * QST + c],     qh[s4][1], ql[s4][1]);
            bsplit(*(const float2*)&Qs[r0 * QST + c + 8],       qh[s4][2], ql[s4][2]);
            bsplit(*(const float2*)&Qs[(r0 + 8) * QST + c + 8], qh[s4][3], ql[s4][3]);
        }
    }
    __syncthreads();

    // ---- cp.async tile loader: thread -> row (tid>>2), 32B chunk (tid&3)
    const int lrow = tid >> 2;
    const int lcb  = (tid & 3) * 32;     // byte offset within 128B row
    const char* srcKh = (const char*)(Kh + (size_t)lrow * DM + hoff) + lcb;
    const char* srcKl = (const char*)(Kl + (size_t)lrow * DM + hoff) + lcb;
    const char* srcV  = (const char*)(V  + (size_t)lrow * DM + hoff) + lcb;
    const unsigned drow = smem_base + lrow * (KST * 2) + lcb;

    auto load_stage = [&](int t, int sbuf) {
        size_t goff = (size_t)t * 64 * DM * 2;   // bytes per 64-row tile step
        unsigned d = drow + sbuf * STAGE_B;
        cp16(d,              srcKh + goff);
        cp16(d + 16,         srcKh + goff + 16);
        cp16(d + TILE_B,     srcKl + goff);
        cp16(d + TILE_B + 16, srcKl + goff + 16);
        cp16(d + 2 * TILE_B, srcV + goff);
        cp16(d + 2 * TILE_B + 16, srcV + goff + 16);
    };

    const int NTILE = SEQ / 64;
    load_stage(0, 0);
    asm volatile("cp.async.commit_group;");
    load_stage(1, 1);
    asm volatile("cp.async.commit_group;");

    // per-warp ldmatrix lane offsets (byte offsets within a plane)
    const unsigned k_off = ((8 * ((lane >> 4) & 1) + (lane & 7)) * KST
                            + 8 * ((lane >> 3) & 1)) * 2;
    const unsigned v_off = ((8 * ((lane >> 3) & 1) + (lane & 7)) * KST
                            + 8 * (lane >> 4)) * 2;

    float o[8][4];
    #pragma unroll
    for (int df = 0; df < 8; df++)
        #pragma unroll
        for (int i = 0; i < 4; i++) o[df][i] = 0.0f;
    float m0 = -1e30f, m1 = -1e30f, l0s = 0.0f, l1s = 0.0f;

    for (int t = 0; t < NTILE; t++) {
        const int buf = t % NSTAGE;
        const unsigned stage = smem_base + buf * STAGE_B;

        asm volatile("cp.async.wait_group 1;");
        __syncthreads();

        // prefetch t+2 into the buffer consumed at t-1 (safe: all passed barrier)
        if (t + 2 < NTILE) load_stage(t + 2, (t + 2) % NSTAGE);
        asm volatile("cp.async.commit_group;");

        // ---- S = Q*K^T (bf16 3-pass)
        float s[8][4];
        #pragma unroll
        for (int nf = 0; nf < 8; nf++)
            #pragma unroll
            for (int i = 0; i < 4; i++) s[nf][i] = 0.0f;

        #pragma unroll
        for (int s4 = 0; s4 < 4; s4++) {
            const int d0 = 16 * s4;
            #pragma unroll
            for (int nfp = 0; nfp < 4; nfp++) {
                const unsigned lo_off = (unsigned)((16 * nfp) * KST + d0) * 2 + k_off;
                unsigned h0, h1, h2, h3, l0, l1, l2, l3;
                ldsm_x4(h0, h1, h2, h3, stage + lo_off);
                ldsm_x4(l0, l1, l2, l3, stage + TILE_B + lo_off);
                mma_bf16(s[2 * nfp],     qh[s4], h0, h1);
                mma_bf16(s[2 * nfp],     ql[s4], h0, h1);
                mma_bf16(s[2 * nfp],     qh[s4], l0, l1);
                mma_bf16(s[2 * nfp + 1], qh[s4], h2, h3);
                mma_bf16(s[2 * nfp + 1], ql[s4], h2, h3);
                mma_bf16(s[2 * nfp + 1], qh[s4], l2, l3);
            }
        }

        // ---- online softmax
        float mx0 = -1e30f, mx1 = -1e30f;
        #pragma unroll
        for (int nf = 0; nf < 8; nf++) {
            mx0 = fmaxf(mx0, fmaxf(s[nf][0], s[nf][1]));
            mx1 = fmaxf(mx1, fmaxf(s[nf][2], s[nf][3]));
        }
        mx0 = fmaxf(mx0, __shfl_xor_sync(0xffffffffu, mx0, 1));
        mx0 = fmaxf(mx0, __shfl_xor_sync(0xffffffffu, mx0, 2));
        mx1 = fmaxf(mx1, __shfl_xor_sync(0xffffffffu, mx1, 1));
        mx1 = fmaxf(mx1, __shfl_xor_sync(0xffffffffu, mx1, 2));

        float nm0 = fmaxf(m0, mx0), nm1 = fmaxf(m1, mx1);
        float a0 = ex2(m0 - nm0), a1 = ex2(m1 - nm1);
        m0 = nm0; m1 = nm1;

        unsigned pp[8][2];
        float ps0 = 0.0f, ps1 = 0.0f;
        #pragma unroll
        for (int nf = 0; nf < 8; nf++) {
            float p0 = ex2(s[nf][0] - nm0);
            float p1 = ex2(s[nf][1] - nm0);
            float p2 = ex2(s[nf][2] - nm1);
            float p3 = ex2(s[nf][3] - nm1);
            ps0 += p0 + p1;
            ps1 += p2 + p3;
            pp[nf][0] = pack_f16(p0, p1);
            pp[nf][1] = pack_f16(p2, p3);
        }
        l0s = l0s * a0 + ps0;
        l1s = l1s * a1 + ps1;

        #pragma unroll
        for (int df = 0; df < 8; df++) {
            o[df][0] *= a0; o[df][1] *= a0;
            o[df][2] *= a1; o[df][3] *= a1;
        }

        // ---- O += P*V
        #pragma unroll
        for (int kf2 = 0; kf2 < 4; kf2++) {
            unsigned af[4];
            af[0] = pp[2 * kf2][0];
            af[1] = pp[2 * kf2][1];
            af[2] = pp[2 * kf2 + 1][0];
            af[3] = pp[2 * kf2 + 1][1];
            #pragma unroll
            for (int dfp = 0; dfp < 4; dfp++) {
                const unsigned off = (unsigned)((16 * kf2) * KST + 16 * dfp) * 2 + v_off;
                unsigned b0, b1, b2, b3;
                ldsm_x4_t(b0, b1, b2, b3, stage + 2 * TILE_B + off);
                mma_f16(o[2 * dfp],     af, b0, b1);
                mma_f16(o[2 * dfp + 1], af, b2, b3);
            }
        }
    }

    // ---- finalize
    l0s += __shfl_xor_sync(0xffffffffu, l0s, 1);
    l0s += __shfl_xor_sync(0xffffffffu, l0s, 2);
    l1s += __shfl_xor_sync(0xffffffffu, l1s, 1);
    l1s += __shfl_xor_sync(0xffffffffu, l1s, 2);
    float i0 = 1.0f / l0s, i1 = 1.0f / l1s;

    const int grow = q0 + warp * 16 + (lane >> 2);
    #pragma unroll
    for (int df = 0; df < 8; df++) {
        int col = hoff + df * 8 + 2 * (lane & 3);
        *(float2*)(O + (size_t)grow * DM + col) =
            make_float2(o[df][0] * i0, o[df][1] * i0);
        *(float2*)(O + (size_t)(grow + 8) * DM + col) =
            make_float2(o[df][2] * i1, o[df][3] * i1);
    }
}

// ---------------------------------------------------------------------------
extern "C" void kernel_launch(void* const* d_in, const int* in_sizes, int n_in,
                              void* d_out, int out_size)
{
    const float* query = (const float*)d_in[0];
    const float* key   = (const float*)d_in[1];
    const float* value = (const float*)d_in[2];
    const float* W_q   = (const float*)d_in[3];
    const float* b_q   = (const float*)d_in[4];
    const float* W_k   = (const float*)d_in[5];
    const float* b_k   = (const float*)d_in[6];
    const float* W_v   = (const float*)d_in[7];
    const float* b_v   = (const float*)d_in[8];
    const float* W_o   = (const float*)d_in[9];
    const float* b_o   = (const float*)d_in[10];
    float* out = (float*)d_out;

    float *Qp, *Ap;
    __nv_bfloat16 *Khp, *Klp;
    __half *Vp;
    cudaGetSymbolAddress((void**)&Qp,  g_Q);
    cudaGetSymbolAddress((void**)&Khp, g_Kh);
    cudaGetSymbolAddress((void**)&Klp, g_Kl);
    cudaGetSymbolAddress((void**)&Vp,  g_V);
    cudaGetSymbolAddress((void**)&Ap,  g_attn);

    const int gsmem = 2 * 2 * GBUF * (int)sizeof(float);   // 81920 B
    const int fsmem = NSTAGE * STAGE_B;                     // 82944 B
    static int attr_set = 0;
    if (!attr_set) {
        cudaFuncSetAttribute(gemm_bf16x3<0>, cudaFuncAttributeMaxDynamicSharedMemorySize, gsmem);
        cudaFuncSetAttribute(gemm_bf16x3<1>, cudaFuncAttributeMaxDynamicSharedMemorySize, gsmem);
        cudaFuncSetAttribute(gemm_bf16x3<2>, cudaFuncAttributeMaxDynamicSharedMemorySize, gsmem);
        cudaFuncSetAttribute(fattn_kernel, cudaFuncAttributeMaxDynamicSharedMemorySize, fsmem);
        attr_set = 1;
    }

    dim3 ggrd(DM / 128, SEQ / 128);
    gemm_bf16x3<0><<<ggrd, 256, gsmem>>>(query, W_q, b_q, Qp, nullptr, SEQ, DM, DM);
    gemm_bf16x3<1><<<ggrd, 256, gsmem>>>(key,   W_k, b_k, Khp, Klp,    SEQ, DM, DM);
    gemm_bf16x3<2><<<ggrd, 256, gsmem>>>(value, W_v, b_v, Vp, nullptr, SEQ, DM, DM);

    dim3 agrd(SEQ / 128, NH);
    fattn_kernel<<<agrd, 256, fsmem>>>(Qp, Khp, Klp, Vp, Ap);

    gemm_bf16x3<0><<<ggrd, 256, gsmem>>>(Ap, W_o, b_o, out, nullptr, SEQ, DM, DM);
}